// round 15
// baseline (speedup 1.0000x reference)
#include <cuda_runtime.h>
#include <cuda_bf16.h>
#include <math.h>
#include <cstdint>

#define BATCH 131072
#define SD 64
#define CD 16
#define HID 256

// ---------------- smem layout (bytes) ----------------
#define SM_A2H   0         // 128 rows x 264 halves (528B stride) = 67584
#define SM_A2L   67584
#define SM_WH    135168    // 256 n-rows x 72 halves (144B stride) = 36864
#define SM_WL    172032
#define SM_W3H   135168    // reuse W buffer: 16 x 264 halves (528B) = 8448
#define SM_W3L   143616
#define SM_B1    208896    // 256 f32
#define SM_B2    209920    // 256 f32
#define SM_B3B   210944    // 16 f32
#define SM_TOTAL 211008

// ---------------- scratch globals ----------------
__device__ float g_W3B[HID * CD];
__device__ float g_b3B[CD];
__device__ float g_pB[BATCH * CD];
__device__ int   g_K;
// pre-converted weight images (exact byte images of the smem staging regions)
__device__ __align__(16) unsigned char g_Wcvt[5][2][36864];  // chunks: W1, W2 k0..3
__device__ __align__(16) unsigned char g_W3cvt[2][8448];     // W3B^T tile hi/lo

// ---------------- helpers ----------------
__device__ __forceinline__ uint32_t smem_u32(const void* p) {
    uint32_t a;
    asm("{ .reg .u64 t; cvta.to.shared.u64 t, %1; cvt.u32.u64 %0, t; }" : "=r"(a) : "l"(p));
    return a;
}
#define CPA16(dst, src) asm volatile("cp.async.cg.shared.global [%0], [%1], 16;" :: "r"((uint32_t)(dst)), "l"(src))
#define CPA_COMMIT()    asm volatile("cp.async.commit_group;" ::: "memory")
#define CPA_WAIT0()     asm volatile("cp.async.wait_group 0;" ::: "memory")

// split (a,b) f32 pair into packed bf16x2 hi + lo (residual)
__device__ __forceinline__ void split2(float a, float b, uint32_t& hi, uint32_t& lo) {
    __nv_bfloat16 ha = __float2bfloat16(a), hb = __float2bfloat16(b);
    float ra = a - __bfloat162float(ha);
    float rb = b - __bfloat162float(hb);
    __nv_bfloat16 la = __float2bfloat16(ra), lb = __float2bfloat16(rb);
    hi = ((uint32_t)__bfloat16_as_ushort(hb) << 16) | (uint32_t)__bfloat16_as_ushort(ha);
    lo = ((uint32_t)__bfloat16_as_ushort(lb) << 16) | (uint32_t)__bfloat16_as_ushort(la);
}

#define LDSM4(v, addr) \
    asm volatile("ldmatrix.sync.aligned.m8n8.x4.shared.b16 {%0,%1,%2,%3}, [%4];" \
        : "=r"((v)[0]), "=r"((v)[1]), "=r"((v)[2]), "=r"((v)[3]) : "r"(addr))

#define MMA(d, a, b0, b1) \
    asm volatile("mma.sync.aligned.m16n8k16.row.col.f32.bf16.bf16.f32 " \
        "{%0,%1,%2,%3}, {%4,%5,%6,%7}, {%8,%9}, {%0,%1,%2,%3};" \
        : "+f"((d)[0]), "+f"((d)[1]), "+f"((d)[2]), "+f"((d)[3]) \
        : "r"((a)[0]), "r"((a)[1]), "r"((a)[2]), "r"((a)[3]), "r"(b0), "r"(b1))

// ---------------- k_prep: W3B = W3 @ Bmat, 16-row partition per block ----------------
__global__ void k_prep(const float* __restrict__ W3, const float* __restrict__ b3,
                       const float* __restrict__ Bm) {
    __shared__ float W3s[16 * 68];   // 16 rows x 64, stride 68 (skewed)
    __shared__ float Bs[64 * 16];
    int blk = blockIdx.x;
    int tid = threadIdx.x;
    if (blk < 16) {
        int r0 = blk * 16;
        {   // stage 16 W3 rows (4 KB) + full Bmat (4 KB), coalesced
            int row = tid >> 4, q = tid & 15;
            ((float4*)(W3s + row * 68))[q] = ((const float4*)(W3 + (r0 + row) * SD))[q];
            ((float4*)Bs)[tid] = ((const float4*)Bm)[tid];
        }
        __syncthreads();
        int r = tid >> 4, j = tid & 15;
        float a = 0.0f;
        const float* row = &W3s[r * 68];
#pragma unroll
        for (int d = 0; d < SD; d++) a = fmaf(row[d], Bs[d * CD + j], a);
        g_W3B[(r0 + r) * CD + j] = a;
    } else {
        if (tid < CD) {
            float a = 0.0f;
            for (int d = 0; d < SD; d++) a = fmaf(b3[d], Bm[d * CD + tid], a);
            g_b3B[tid] = a;
        }
        if (tid == 0) g_K = 0;
    }
}

// ---------------- k_wcvt: convert weights to fragment-layout bf16 hi/lo once ----------
__global__ void k_wcvt(const float* __restrict__ W1, const float* __restrict__ W2) {
    int c = blockIdx.x;
    int n = threadIdx.x;
    if (c < 5) {
        const float* W = (c == 0) ? W1 : W2;
        int krow0 = (c == 0) ? 0 : (c - 1) * 64;
#pragma unroll
        for (int it = 0; it < 8; it++) {
            int kb = krow0 + it * 8;
            uint32_t h[4], l[4];
#pragma unroll
            for (int q = 0; q < 4; q++) {
                float w0 = W[(kb + 2 * q) * HID + n];
                float w1 = W[(kb + 2 * q + 1) * HID + n];
                split2(w0, w1, h[q], l[q]);
            }
            *(uint4*)(g_Wcvt[c][0] + n * 144 + it * 16) = make_uint4(h[0], h[1], h[2], h[3]);
            *(uint4*)(g_Wcvt[c][1] + n * 144 + it * 16) = make_uint4(l[0], l[1], l[2], l[3]);
        }
    } else {
#pragma unroll
        for (int it = 0; it < 8; it++) {
            int pid = n + it * 256;
            int nn = pid & 15, k2 = pid >> 4;
            float v0 = g_W3B[(2 * k2) * CD + nn];
            float v1 = g_W3B[(2 * k2 + 1) * CD + nn];
            uint32_t hi, lo;
            split2(v0, v1, hi, lo);
            *(uint32_t*)(g_W3cvt[0] + nn * 528 + k2 * 4) = hi;
            *(uint32_t*)(g_W3cvt[1] + nn * 528 + k2 * 4) = lo;
        }
    }
}

// stage pre-converted W chunk into smem via cp.async (no ALU)
__device__ __forceinline__ void stage_wchunk(uint32_t smb, int c, int tid) {
    const uint4* sH = (const uint4*)g_Wcvt[c][0];
    const uint4* sL = (const uint4*)g_Wcvt[c][1];
#pragma unroll
    for (int i = tid; i < 2304; i += 256) {
        CPA16(smb + SM_WH + i * 16, sH + i);
        CPA16(smb + SM_WL + i * 16, sL + i);
    }
    CPA_COMMIT();
}

// ---------------- fused MLP via mma.sync (R13 winner, unchanged) ----------------
__global__ void __launch_bounds__(256, 1) k_mlp(
    const float* __restrict__ x, const float* __restrict__ t,
    const float* __restrict__ W1, const float* __restrict__ b1,
    const float* __restrict__ b2)
{
    extern __shared__ char sm[];
    uint32_t smb = smem_u32(sm);
    int tid = threadIdx.x, wid = tid >> 5, lid = tid & 31;
    int slab = wid * 16;
    int row0 = blockIdx.x * 128;
    int r0 = lid >> 2, cq = 2 * (lid & 3);

    // issue W1 chunk copy immediately (overlaps everything below)
    stage_wchunk(smb, 0, tid);

    // coop: biases
    float t0 = t[0];
    ((float*)(sm + SM_B1))[tid] = fmaf(t0, W1[64 * HID + tid], b1[tid]);
    ((float*)(sm + SM_B2))[tid] = b2[tid];
    if (tid < CD) ((float*)(sm + SM_B3B))[tid] = g_b3B[tid];

    // per-warp: stage own 16 rows of X into own region of A2H, stride 68 f32
    float* Xs = (float*)(sm + SM_A2H + wid * 8448);
#pragma unroll
    for (int i = 0; i < 8; i++) {
        int fid = i * 32 + lid;
        int r = fid >> 4, c4 = fid & 15;
        float4 v = *(const float4*)&x[(row0 + slab + r) * SD + c4 * 4];
        *(float4*)&Xs[r * 68 + c4 * 4] = v;
    }
    __syncwarp();

    // X fragments (bf16 hi/lo) in regs: 4 k-tiles
    uint32_t xh[4][4], xl[4][4];
#pragma unroll
    for (int kt = 0; kt < 4; kt++) {
        int cb = kt * 16 + cq;
        float2 v00 = *(float2*)&Xs[r0 * 68 + cb];
        float2 v10 = *(float2*)&Xs[(r0 + 8) * 68 + cb];
        float2 v01 = *(float2*)&Xs[r0 * 68 + cb + 8];
        float2 v11 = *(float2*)&Xs[(r0 + 8) * 68 + cb + 8];
        split2(v00.x, v00.y, xh[kt][0], xl[kt][0]);
        split2(v10.x, v10.y, xh[kt][1], xl[kt][1]);
        split2(v01.x, v01.y, xh[kt][2], xl[kt][2]);
        split2(v11.x, v11.y, xh[kt][3], xl[kt][3]);
    }
    __syncwarp();
    CPA_WAIT0();
    __syncthreads();   // W1 staged + X frags done (X region freed)

    // ---- Layer 1: D[16x256] = X @ W1 (bf16 3-product) ----
    float d[32][4];
#pragma unroll
    for (int m = 0; m < 32; m++)
#pragma unroll
        for (int q = 0; q < 4; q++) d[m][q] = 0.0f;

#pragma unroll
    for (int kt = 0; kt < 4; kt++) {
#pragma unroll
        for (int n2 = 0; n2 < 16; n2++) {
            uint32_t bh[4], bl[4];
            uint32_t brow = n2 * 16 + ((lid >> 4) << 3) + (lid & 7);
            uint32_t baddr = smb + SM_WH + brow * 144 + (kt * 16 + (lid & 8)) * 2;
            LDSM4(bh, baddr);
            LDSM4(bl, baddr + (SM_WL - SM_WH));
            MMA(d[2 * n2],     xh[kt], bh[0], bh[1]);
            MMA(d[2 * n2],     xh[kt], bl[0], bl[1]);
            MMA(d[2 * n2],     xl[kt], bh[0], bh[1]);
            MMA(d[2 * n2 + 1], xh[kt], bh[2], bh[3]);
            MMA(d[2 * n2 + 1], xh[kt], bl[2], bl[3]);
            MMA(d[2 * n2 + 1], xl[kt], bh[2], bh[3]);
        }
    }

    // ---- relu + bias1 -> A2 (warp-private smem, bf16 hi/lo) ----
    {
        const float* bs1 = (const float*)(sm + SM_B1);
#pragma unroll
        for (int m = 0; m < 32; m++) {
            int c = m * 8 + cq;
            float2 bv = *(const float2*)&bs1[c];
            float h0 = fmaxf(d[m][0] + bv.x, 0.0f);
            float h1 = fmaxf(d[m][1] + bv.y, 0.0f);
            float h2 = fmaxf(d[m][2] + bv.x, 0.0f);
            float h3 = fmaxf(d[m][3] + bv.y, 0.0f);
            uint32_t hi01, lo01, hi23, lo23;
            split2(h0, h1, hi01, lo01);
            split2(h2, h3, hi23, lo23);
            int ra = slab + r0;
            *(uint32_t*)(sm + SM_A2H + ra * 528 + c * 2) = hi01;
            *(uint32_t*)(sm + SM_A2L + ra * 528 + c * 2) = lo01;
            *(uint32_t*)(sm + SM_A2H + (ra + 8) * 528 + c * 2) = hi23;
            *(uint32_t*)(sm + SM_A2L + (ra + 8) * 528 + c * 2) = lo23;
        }
    }
    __syncthreads();

    // zero accum for layer 2
#pragma unroll
    for (int m = 0; m < 32; m++)
#pragma unroll
        for (int q = 0; q < 4; q++) d[m][q] = 0.0f;

    // ---- Layer 2: 4 K-chunks of 64 (bf16 3-product), cp.async staging ----
#pragma unroll 1
    for (int kc = 0; kc < 4; kc++) {
        stage_wchunk(smb, 1 + kc, tid);
        CPA_WAIT0();
        __syncthreads();
#pragma unroll
        for (int kt = 0; kt < 4; kt++) {
            uint32_t ah[4], al[4];
            uint32_t arow = slab + (lid & 15);
            uint32_t acol = kc * 64 + kt * 16 + ((lid >> 4) << 3);
            uint32_t aaddr = smb + SM_A2H + arow * 528 + acol * 2;
            LDSM4(ah, aaddr);
            LDSM4(al, aaddr + (SM_A2L - SM_A2H));
#pragma unroll
            for (int n2 = 0; n2 < 16; n2++) {
                uint32_t bh[4], bl[4];
                uint32_t brow = n2 * 16 + ((lid >> 4) << 3) + (lid & 7);
                uint32_t baddr = smb + SM_WH + brow * 144 + (kt * 16 + (lid & 8)) * 2;
                LDSM4(bh, baddr);
                LDSM4(bl, baddr + (SM_WL - SM_WH));
                MMA(d[2 * n2],     ah, bh[0], bh[1]);
                MMA(d[2 * n2],     ah, bl[0], bl[1]);
                MMA(d[2 * n2],     al, bh[0], bh[1]);
                MMA(d[2 * n2 + 1], ah, bh[2], bh[3]);
                MMA(d[2 * n2 + 1], ah, bl[2], bl[3]);
                MMA(d[2 * n2 + 1], al, bh[2], bh[3]);
            }
        }
        __syncthreads();
    }

    // ---- issue W3B^T tile copy (overlaps with A3 fragment compute) ----
    {
        const uint4* sH = (const uint4*)g_W3cvt[0];
        const uint4* sL = (const uint4*)g_W3cvt[1];
#pragma unroll
        for (int i = tid; i < 528; i += 256) {
            CPA16(smb + SM_W3H + i * 16, sH + i);
            CPA16(smb + SM_W3L + i * 16, sL + i);
        }
        CPA_COMMIT();
    }

    // ---- relu + bias2 -> A3 fragments (bf16 hi/lo) ----
    uint32_t a3h[16][4], a3l[16][4];
    {
        const float* bs2 = (const float*)(sm + SM_B2);
#pragma unroll
        for (int g = 0; g < 16; g++) {
#pragma unroll
            for (int hh = 0; hh < 2; hh++) {
                int m = 2 * g + hh;
                int c = m * 8 + cq;
                float2 bv = *(const float2*)&bs2[c];
                float h0 = fmaxf(d[m][0] + bv.x, 0.0f);
                float h1 = fmaxf(d[m][1] + bv.y, 0.0f);
                float h2 = fmaxf(d[m][2] + bv.x, 0.0f);
                float h3 = fmaxf(d[m][3] + bv.y, 0.0f);
                split2(h0, h1, a3h[g][2 * hh],     a3l[g][2 * hh]);
                split2(h2, h3, a3h[g][2 * hh + 1], a3l[g][2 * hh + 1]);
            }
        }
    }
    CPA_WAIT0();
    __syncthreads();

    // ---- Layer 3: pB[16x16] = H2 @ W3B (bf16 3-product) ----
    float d3a[4] = {0.f, 0.f, 0.f, 0.f};
    float d3b[4] = {0.f, 0.f, 0.f, 0.f};
#pragma unroll
    for (int g = 0; g < 16; g++) {
        uint32_t bh[4], bl[4];
        uint32_t brow = ((lid >> 4) << 3) + (lid & 7);
        uint32_t baddr = smb + SM_W3H + brow * 528 + (g * 16 + (lid & 8)) * 2;
        LDSM4(bh, baddr);
        LDSM4(bl, baddr + (SM_W3L - SM_W3H));
        MMA(d3a, a3h[g], bh[0], bh[1]);
        MMA(d3a, a3h[g], bl[0], bl[1]);
        MMA(d3a, a3l[g], bh[0], bh[1]);
        MMA(d3b, a3h[g], bh[2], bh[3]);
        MMA(d3b, a3h[g], bl[2], bl[3]);
        MMA(d3b, a3l[g], bh[2], bh[3]);
    }

    // ---- epilogue: add b3B, store pB ----
    {
        const float* b3s = (const float*)(sm + SM_B3B);
        float2 bva = *(const float2*)&b3s[cq];
        float2 bvb = *(const float2*)&b3s[8 + cq];
        int r = row0 + slab + r0;
        float2 v;
        v = make_float2(d3a[0] + bva.x, d3a[1] + bva.y);
        *(float2*)&g_pB[r * CD + cq] = v;
        v = make_float2(d3b[0] + bvb.x, d3b[1] + bvb.y);
        *(float2*)&g_pB[r * CD + 8 + cq] = v;
        v = make_float2(d3a[2] + bva.x, d3a[3] + bva.y);
        *(float2*)&g_pB[(r + 8) * CD + cq] = v;
        v = make_float2(d3b[2] + bvb.x, d3b[3] + bvb.y);
        *(float2*)&g_pB[(r + 8) * CD + 8 + cq] = v;
    }
}

// ---------------- k_count: FULLY analytic K (clamping handled), no loop ----------------
// Unclamped coord: delta_j(n) = 0.1*0.9^(n-1)*pb_j. Coord with |pb_j|>1 clamps at
// n_j = floor(ln(1-1/|pb_j|)/ln 0.9)+1 and contributes 0 delta after.
// s2(n) = 0.01*0.81^(n-1)*A(n),  A(n) = sum_{n <= n_j} pb_j^2  (monotone non-increasing).
// K = first n with s2(n) < 1e-6 (== res < TOL), capped at 200. Binary search on n.
__global__ void k_count() {
    int row = blockIdx.x * 256 + threadIdx.x;
    const float4* pbp = (const float4*)&g_pB[row * CD];
    float pb2[16];
    int   nj[16];
#pragma unroll
    for (int q = 0; q < 4; q++) {
        float4 v = pbp[q];
        float c[4] = {v.x, v.y, v.z, v.w};
#pragma unroll
        for (int e = 0; e < 4; e++) {
            int j = 4 * q + e;
            float ap = fabsf(c[e]);
            pb2[j] = c[e] * c[e];
            if (ap > 1.0f) {
                double R = log(1.0 - 1.0 / (double)ap) * (1.0 / -0.10536051565782628);
                nj[j] = (int)floor(R) + 1;     // first step where clamp engages
            } else {
                nj[j] = 0x7fffffff;            // never clamps
            }
        }
    }

    // f(n) = (s2(n) >= 1e-6)  <=>  0.81^(n-1) * A(n) >= 1e-4
    auto f_ge = [&](int n) -> bool {
        double An = 0.0;
#pragma unroll
        for (int j = 0; j < 16; j++)
            if (n <= nj[j]) An += (double)pb2[j];
        return pow(0.81, (double)(n - 1)) * An >= 1e-4;
    };

    int K;
    if (!f_ge(1)) {
        K = 1;                        // converged after the first iteration
    } else if (f_ge(199)) {
        K = 200;                      // hits the MAX_ITERS cap
    } else {
        int lo = 1, hi = 199;         // f_ge(lo)=true, f_ge(hi)=false
        while (hi - lo > 1) {
            int mid = (lo + hi) >> 1;
            if (f_ge(mid)) lo = mid; else hi = mid;
        }
        K = hi;
    }

    int v = K;
#pragma unroll
    for (int o = 16; o > 0; o >>= 1)
        v = max(v, __shfl_xor_sync(0xffffffffu, v, o));
    if ((threadIdx.x & 31) == 0) atomicMax(&g_K, v);
}

// ---------------- k_final: u = clamp(-(1 - 0.9^(K+6)) * pB), thread per float4 ------
__global__ void k_final(float* __restrict__ out) {
    int idx = blockIdx.x * 256 + threadIdx.x;    // over BATCH*CD/4 float4s
    int n = g_K + 6;
    float f = -(1.0f - powf(0.9f, (float)n));
    float4 v = ((const float4*)g_pB)[idx];
    float4 u;
    u.x = fminf(fmaxf(f * v.x, -1.0f), 1.0f);
    u.y = fminf(fmaxf(f * v.y, -1.0f), 1.0f);
    u.z = fminf(fmaxf(f * v.z, -1.0f), 1.0f);
    u.w = fminf(fmaxf(f * v.w, -1.0f), 1.0f);
    ((float4*)out)[idx] = u;
}

// ---------------------------------------------------------------------------
extern "C" void kernel_launch(void* const* d_in, const int* in_sizes, int n_in,
                              void* d_out, int out_size) {
    const float* x  = (const float*)d_in[0];
    const float* t  = (const float*)d_in[1];
    const float* W1 = (const float*)d_in[2];
    const float* b1 = (const float*)d_in[3];
    const float* W2 = (const float*)d_in[4];
    const float* b2 = (const float*)d_in[5];
    const float* W3 = (const float*)d_in[6];
    const float* b3 = (const float*)d_in[7];
    const float* Bm = (const float*)d_in[8];
    float* out = (float*)d_out;

    cudaFuncSetAttribute(k_mlp, cudaFuncAttributeMaxDynamicSharedMemorySize, SM_TOTAL);

    k_prep<<<17, 256>>>(W3, b3, Bm);
    k_wcvt<<<6, 256>>>(W1, W2);
    k_mlp<<<BATCH / 128, 256, SM_TOTAL>>>(x, t, W1, b1, b2);
    k_count<<<BATCH / 256, 256>>>();
    k_final<<<BATCH * CD / 4 / 256, 256>>>(out);
}

// round 16
// speedup vs baseline: 2.7114x; 2.7114x over previous
#include <cuda_runtime.h>
#include <cuda_bf16.h>
#include <math.h>
#include <cstdint>

#define BATCH 131072
#define SD 64
#define CD 16
#define HID 256

// ---------------- smem layout (bytes) ----------------
#define SM_A2H   0         // 128 rows x 264 halves (528B stride) = 67584
#define SM_A2L   67584
#define SM_WH    135168    // 256 n-rows x 72 halves (144B stride) = 36864
#define SM_WL    172032
#define SM_W3H   135168    // reuse W buffer: 16 x 264 halves (528B) = 8448
#define SM_W3L   143616
#define SM_B1    208896    // 256 f32
#define SM_B2    209920    // 256 f32
#define SM_B3B   210944    // 16 f32
#define SM_TOTAL 211008

// ---------------- scratch globals ----------------
__device__ float g_W3B[HID * CD];
__device__ float g_b3B[CD];
__device__ float g_pB[BATCH * CD];
__device__ int   g_K;
// pre-converted weight images (exact byte images of the smem staging regions)
__device__ __align__(16) unsigned char g_Wcvt[5][2][36864];  // chunks: W1, W2 k0..3
__device__ __align__(16) unsigned char g_W3cvt[2][8448];     // W3B^T tile hi/lo

// ---------------- helpers ----------------
__device__ __forceinline__ uint32_t smem_u32(const void* p) {
    uint32_t a;
    asm("{ .reg .u64 t; cvta.to.shared.u64 t, %1; cvt.u32.u64 %0, t; }" : "=r"(a) : "l"(p));
    return a;
}
#define CPA16(dst, src) asm volatile("cp.async.cg.shared.global [%0], [%1], 16;" :: "r"((uint32_t)(dst)), "l"(src))
#define CPA_COMMIT()    asm volatile("cp.async.commit_group;" ::: "memory")
#define CPA_WAIT0()     asm volatile("cp.async.wait_group 0;" ::: "memory")

// split (a,b) f32 pair into packed bf16x2 hi + lo (residual)
__device__ __forceinline__ void split2(float a, float b, uint32_t& hi, uint32_t& lo) {
    __nv_bfloat16 ha = __float2bfloat16(a), hb = __float2bfloat16(b);
    float ra = a - __bfloat162float(ha);
    float rb = b - __bfloat162float(hb);
    __nv_bfloat16 la = __float2bfloat16(ra), lb = __float2bfloat16(rb);
    hi = ((uint32_t)__bfloat16_as_ushort(hb) << 16) | (uint32_t)__bfloat16_as_ushort(ha);
    lo = ((uint32_t)__bfloat16_as_ushort(lb) << 16) | (uint32_t)__bfloat16_as_ushort(la);
}

#define LDSM4(v, addr) \
    asm volatile("ldmatrix.sync.aligned.m8n8.x4.shared.b16 {%0,%1,%2,%3}, [%4];" \
        : "=r"((v)[0]), "=r"((v)[1]), "=r"((v)[2]), "=r"((v)[3]) : "r"(addr))

#define MMA(d, a, b0, b1) \
    asm volatile("mma.sync.aligned.m16n8k16.row.col.f32.bf16.bf16.f32 " \
        "{%0,%1,%2,%3}, {%4,%5,%6,%7}, {%8,%9}, {%0,%1,%2,%3};" \
        : "+f"((d)[0]), "+f"((d)[1]), "+f"((d)[2]), "+f"((d)[3]) \
        : "r"((a)[0]), "r"((a)[1]), "r"((a)[2]), "r"((a)[3]), "r"(b0), "r"(b1))

// ---------------- k_prep: W3B = W3 @ Bmat, 16-row partition per block ----------------
__global__ void k_prep(const float* __restrict__ W3, const float* __restrict__ b3,
                       const float* __restrict__ Bm) {
    __shared__ float W3s[16 * 68];   // 16 rows x 64, stride 68 (skewed)
    __shared__ float Bs[64 * 16];
    int blk = blockIdx.x;
    int tid = threadIdx.x;
    if (blk < 16) {
        int r0 = blk * 16;
        {   // stage 16 W3 rows (4 KB) + full Bmat (4 KB), coalesced
            int row = tid >> 4, q = tid & 15;
            ((float4*)(W3s + row * 68))[q] = ((const float4*)(W3 + (r0 + row) * SD))[q];
            ((float4*)Bs)[tid] = ((const float4*)Bm)[tid];
        }
        __syncthreads();
        int r = tid >> 4, j = tid & 15;
        float a = 0.0f;
        const float* row = &W3s[r * 68];
#pragma unroll
        for (int d = 0; d < SD; d++) a = fmaf(row[d], Bs[d * CD + j], a);
        g_W3B[(r0 + r) * CD + j] = a;
    } else {
        if (tid < CD) {
            float a = 0.0f;
            for (int d = 0; d < SD; d++) a = fmaf(b3[d], Bm[d * CD + tid], a);
            g_b3B[tid] = a;
        }
        if (tid == 0) g_K = 0;
    }
}

// ---------------- k_wcvt: convert weights to fragment-layout bf16 hi/lo once ----------
__global__ void k_wcvt(const float* __restrict__ W1, const float* __restrict__ W2) {
    int c = blockIdx.x;
    int n = threadIdx.x;
    if (c < 5) {
        const float* W = (c == 0) ? W1 : W2;
        int krow0 = (c == 0) ? 0 : (c - 1) * 64;
#pragma unroll
        for (int it = 0; it < 8; it++) {
            int kb = krow0 + it * 8;
            uint32_t h[4], l[4];
#pragma unroll
            for (int q = 0; q < 4; q++) {
                float w0 = W[(kb + 2 * q) * HID + n];
                float w1 = W[(kb + 2 * q + 1) * HID + n];
                split2(w0, w1, h[q], l[q]);
            }
            *(uint4*)(g_Wcvt[c][0] + n * 144 + it * 16) = make_uint4(h[0], h[1], h[2], h[3]);
            *(uint4*)(g_Wcvt[c][1] + n * 144 + it * 16) = make_uint4(l[0], l[1], l[2], l[3]);
        }
    } else {
#pragma unroll
        for (int it = 0; it < 8; it++) {
            int pid = n + it * 256;
            int nn = pid & 15, k2 = pid >> 4;
            float v0 = g_W3B[(2 * k2) * CD + nn];
            float v1 = g_W3B[(2 * k2 + 1) * CD + nn];
            uint32_t hi, lo;
            split2(v0, v1, hi, lo);
            *(uint32_t*)(g_W3cvt[0] + nn * 528 + k2 * 4) = hi;
            *(uint32_t*)(g_W3cvt[1] + nn * 528 + k2 * 4) = lo;
        }
    }
}

// stage pre-converted W chunk into smem via cp.async (no ALU)
__device__ __forceinline__ void stage_wchunk(uint32_t smb, int c, int tid) {
    const uint4* sH = (const uint4*)g_Wcvt[c][0];
    const uint4* sL = (const uint4*)g_Wcvt[c][1];
#pragma unroll
    for (int i = tid; i < 2304; i += 256) {
        CPA16(smb + SM_WH + i * 16, sH + i);
        CPA16(smb + SM_WL + i * 16, sL + i);
    }
    CPA_COMMIT();
}

// ---------------- fused MLP via mma.sync (R13 winner, unchanged) ----------------
__global__ void __launch_bounds__(256, 1) k_mlp(
    const float* __restrict__ x, const float* __restrict__ t,
    const float* __restrict__ W1, const float* __restrict__ b1,
    const float* __restrict__ b2)
{
    extern __shared__ char sm[];
    uint32_t smb = smem_u32(sm);
    int tid = threadIdx.x, wid = tid >> 5, lid = tid & 31;
    int slab = wid * 16;
    int row0 = blockIdx.x * 128;
    int r0 = lid >> 2, cq = 2 * (lid & 3);

    // issue W1 chunk copy immediately (overlaps everything below)
    stage_wchunk(smb, 0, tid);

    // coop: biases
    float t0 = t[0];
    ((float*)(sm + SM_B1))[tid] = fmaf(t0, W1[64 * HID + tid], b1[tid]);
    ((float*)(sm + SM_B2))[tid] = b2[tid];
    if (tid < CD) ((float*)(sm + SM_B3B))[tid] = g_b3B[tid];

    // per-warp: stage own 16 rows of X into own region of A2H, stride 68 f32
    float* Xs = (float*)(sm + SM_A2H + wid * 8448);
#pragma unroll
    for (int i = 0; i < 8; i++) {
        int fid = i * 32 + lid;
        int r = fid >> 4, c4 = fid & 15;
        float4 v = *(const float4*)&x[(row0 + slab + r) * SD + c4 * 4];
        *(float4*)&Xs[r * 68 + c4 * 4] = v;
    }
    __syncwarp();

    // X fragments (bf16 hi/lo) in regs: 4 k-tiles
    uint32_t xh[4][4], xl[4][4];
#pragma unroll
    for (int kt = 0; kt < 4; kt++) {
        int cb = kt * 16 + cq;
        float2 v00 = *(float2*)&Xs[r0 * 68 + cb];
        float2 v10 = *(float2*)&Xs[(r0 + 8) * 68 + cb];
        float2 v01 = *(float2*)&Xs[r0 * 68 + cb + 8];
        float2 v11 = *(float2*)&Xs[(r0 + 8) * 68 + cb + 8];
        split2(v00.x, v00.y, xh[kt][0], xl[kt][0]);
        split2(v10.x, v10.y, xh[kt][1], xl[kt][1]);
        split2(v01.x, v01.y, xh[kt][2], xl[kt][2]);
        split2(v11.x, v11.y, xh[kt][3], xl[kt][3]);
    }
    __syncwarp();
    CPA_WAIT0();
    __syncthreads();   // W1 staged + X frags done (X region freed)

    // ---- Layer 1: D[16x256] = X @ W1 (bf16 3-product) ----
    float d[32][4];
#pragma unroll
    for (int m = 0; m < 32; m++)
#pragma unroll
        for (int q = 0; q < 4; q++) d[m][q] = 0.0f;

#pragma unroll
    for (int kt = 0; kt < 4; kt++) {
#pragma unroll
        for (int n2 = 0; n2 < 16; n2++) {
            uint32_t bh[4], bl[4];
            uint32_t brow = n2 * 16 + ((lid >> 4) << 3) + (lid & 7);
            uint32_t baddr = smb + SM_WH + brow * 144 + (kt * 16 + (lid & 8)) * 2;
            LDSM4(bh, baddr);
            LDSM4(bl, baddr + (SM_WL - SM_WH));
            MMA(d[2 * n2],     xh[kt], bh[0], bh[1]);
            MMA(d[2 * n2],     xh[kt], bl[0], bl[1]);
            MMA(d[2 * n2],     xl[kt], bh[0], bh[1]);
            MMA(d[2 * n2 + 1], xh[kt], bh[2], bh[3]);
            MMA(d[2 * n2 + 1], xh[kt], bl[2], bl[3]);
            MMA(d[2 * n2 + 1], xl[kt], bh[2], bh[3]);
        }
    }

    // ---- relu + bias1 -> A2 (warp-private smem, bf16 hi/lo) ----
    {
        const float* bs1 = (const float*)(sm + SM_B1);
#pragma unroll
        for (int m = 0; m < 32; m++) {
            int c = m * 8 + cq;
            float2 bv = *(const float2*)&bs1[c];
            float h0 = fmaxf(d[m][0] + bv.x, 0.0f);
            float h1 = fmaxf(d[m][1] + bv.y, 0.0f);
            float h2 = fmaxf(d[m][2] + bv.x, 0.0f);
            float h3 = fmaxf(d[m][3] + bv.y, 0.0f);
            uint32_t hi01, lo01, hi23, lo23;
            split2(h0, h1, hi01, lo01);
            split2(h2, h3, hi23, lo23);
            int ra = slab + r0;
            *(uint32_t*)(sm + SM_A2H + ra * 528 + c * 2) = hi01;
            *(uint32_t*)(sm + SM_A2L + ra * 528 + c * 2) = lo01;
            *(uint32_t*)(sm + SM_A2H + (ra + 8) * 528 + c * 2) = hi23;
            *(uint32_t*)(sm + SM_A2L + (ra + 8) * 528 + c * 2) = lo23;
        }
    }
    __syncthreads();

    // zero accum for layer 2
#pragma unroll
    for (int m = 0; m < 32; m++)
#pragma unroll
        for (int q = 0; q < 4; q++) d[m][q] = 0.0f;

    // ---- Layer 2: 4 K-chunks of 64 (bf16 3-product), cp.async staging ----
#pragma unroll 1
    for (int kc = 0; kc < 4; kc++) {
        stage_wchunk(smb, 1 + kc, tid);
        CPA_WAIT0();
        __syncthreads();
#pragma unroll
        for (int kt = 0; kt < 4; kt++) {
            uint32_t ah[4], al[4];
            uint32_t arow = slab + (lid & 15);
            uint32_t acol = kc * 64 + kt * 16 + ((lid >> 4) << 3);
            uint32_t aaddr = smb + SM_A2H + arow * 528 + acol * 2;
            LDSM4(ah, aaddr);
            LDSM4(al, aaddr + (SM_A2L - SM_A2H));
#pragma unroll
            for (int n2 = 0; n2 < 16; n2++) {
                uint32_t bh[4], bl[4];
                uint32_t brow = n2 * 16 + ((lid >> 4) << 3) + (lid & 7);
                uint32_t baddr = smb + SM_WH + brow * 144 + (kt * 16 + (lid & 8)) * 2;
                LDSM4(bh, baddr);
                LDSM4(bl, baddr + (SM_WL - SM_WH));
                MMA(d[2 * n2],     ah, bh[0], bh[1]);
                MMA(d[2 * n2],     ah, bl[0], bl[1]);
                MMA(d[2 * n2],     al, bh[0], bh[1]);
                MMA(d[2 * n2 + 1], ah, bh[2], bh[3]);
                MMA(d[2 * n2 + 1], ah, bl[2], bl[3]);
                MMA(d[2 * n2 + 1], al, bh[2], bh[3]);
            }
        }
        __syncthreads();
    }

    // ---- issue W3B^T tile copy (overlaps with A3 fragment compute) ----
    {
        const uint4* sH = (const uint4*)g_W3cvt[0];
        const uint4* sL = (const uint4*)g_W3cvt[1];
#pragma unroll
        for (int i = tid; i < 528; i += 256) {
            CPA16(smb + SM_W3H + i * 16, sH + i);
            CPA16(smb + SM_W3L + i * 16, sL + i);
        }
        CPA_COMMIT();
    }

    // ---- relu + bias2 -> A3 fragments (bf16 hi/lo) ----
    uint32_t a3h[16][4], a3l[16][4];
    {
        const float* bs2 = (const float*)(sm + SM_B2);
#pragma unroll
        for (int g = 0; g < 16; g++) {
#pragma unroll
            for (int hh = 0; hh < 2; hh++) {
                int m = 2 * g + hh;
                int c = m * 8 + cq;
                float2 bv = *(const float2*)&bs2[c];
                float h0 = fmaxf(d[m][0] + bv.x, 0.0f);
                float h1 = fmaxf(d[m][1] + bv.y, 0.0f);
                float h2 = fmaxf(d[m][2] + bv.x, 0.0f);
                float h3 = fmaxf(d[m][3] + bv.y, 0.0f);
                split2(h0, h1, a3h[g][2 * hh],     a3l[g][2 * hh]);
                split2(h2, h3, a3h[g][2 * hh + 1], a3l[g][2 * hh + 1]);
            }
        }
    }
    CPA_WAIT0();
    __syncthreads();

    // ---- Layer 3: pB[16x16] = H2 @ W3B (bf16 3-product) ----
    float d3a[4] = {0.f, 0.f, 0.f, 0.f};
    float d3b[4] = {0.f, 0.f, 0.f, 0.f};
#pragma unroll
    for (int g = 0; g < 16; g++) {
        uint32_t bh[4], bl[4];
        uint32_t brow = ((lid >> 4) << 3) + (lid & 7);
        uint32_t baddr = smb + SM_W3H + brow * 528 + (g * 16 + (lid & 8)) * 2;
        LDSM4(bh, baddr);
        LDSM4(bl, baddr + (SM_W3L - SM_W3H));
        MMA(d3a, a3h[g], bh[0], bh[1]);
        MMA(d3a, a3h[g], bl[0], bl[1]);
        MMA(d3a, a3l[g], bh[0], bh[1]);
        MMA(d3b, a3h[g], bh[2], bh[3]);
        MMA(d3b, a3h[g], bl[2], bl[3]);
        MMA(d3b, a3l[g], bh[2], bh[3]);
    }

    // ---- epilogue: add b3B, store pB ----
    {
        const float* b3s = (const float*)(sm + SM_B3B);
        float2 bva = *(const float2*)&b3s[cq];
        float2 bvb = *(const float2*)&b3s[8 + cq];
        int r = row0 + slab + r0;
        float2 v;
        v = make_float2(d3a[0] + bva.x, d3a[1] + bva.y);
        *(float2*)&g_pB[r * CD + cq] = v;
        v = make_float2(d3b[0] + bvb.x, d3b[1] + bvb.y);
        *(float2*)&g_pB[r * CD + 8 + cq] = v;
        v = make_float2(d3a[2] + bva.x, d3a[3] + bva.y);
        *(float2*)&g_pB[(r + 8) * CD + cq] = v;
        v = make_float2(d3b[2] + bvb.x, d3b[3] + bvb.y);
        *(float2*)&g_pB[(r + 8) * CD + 8 + cq] = v;
    }
}

// ---------------- k_count: analytic K in fp32 via clamp-event segment walk ----------
// Unclamped: delta_j(n) = 0.1*0.9^(n-1)*pb_j. |pb_j|>1 clamps at
// n_j = floor(ln(1-1/|pb_j|)/ln0.9)+1; contributes 0 delta after.
// s2(n) = 0.01*0.81^(n-1)*A(n), A piecewise-constant dropping at events.
// Walk segments; within a segment crossing n0 = floor(ln(A*1e4)*4.7456)+2.
__global__ void k_count() {
    int row = blockIdx.x * 256 + threadIdx.x;
    const float4* pbp = (const float4*)&g_pB[row * CD];
    float pb2[16], nj[16];
#pragma unroll
    for (int q = 0; q < 4; q++) {
        float4 v = pbp[q];
        float c[4] = {v.x, v.y, v.z, v.w};
#pragma unroll
        for (int e = 0; e < 4; e++) {
            int j = 4 * q + e;
            float ap = fabsf(c[e]);
            pb2[j] = c[e] * c[e];
            nj[j] = (ap > 1.0f)
                ? floorf(logf(1.0f - 1.0f / ap) * -9.49122334f) + 1.0f
                : 1e30f;
        }
    }

    float A = 0.0f;
#pragma unroll
    for (int j = 0; j < 16; j++) A += pb2[j];

    int K = 200;
    float nstart = 1.0f;
    for (int it = 0; it < 17; it++) {
        // next clamp event at or after nstart
        float nev = 1e30f;
#pragma unroll
        for (int j = 0; j < 16; j++)
            if (nj[j] >= nstart) nev = fminf(nev, nj[j]);
        // crossing candidate with current A (A valid for n in [nstart, nev])
        int n0;
        if (A < 1e-30f) {
            n0 = (int)nstart;                       // s2 == 0 here
        } else {
            float L = logf(A * 1e4f) * 4.74560547f; // 1/ln(1/0.81)
            n0 = (int)floorf(L) + 2;
            if (n0 < (int)nstart) n0 = (int)nstart;
        }
        if ((float)n0 <= nev || nev > 2e29f) { K = n0; break; }
        // crossing beyond this segment: remove coords clamping at nev
#pragma unroll
        for (int j = 0; j < 16; j++)
            if (nj[j] == nev) A -= pb2[j];
        if (A < 0.0f) A = 0.0f;
        nstart = nev + 1.0f;
    }
    if (K > 200) K = 200;
    if (K < 1) K = 1;

    int v = K;
#pragma unroll
    for (int o = 16; o > 0; o >>= 1)
        v = max(v, __shfl_xor_sync(0xffffffffu, v, o));
    if ((threadIdx.x & 31) == 0) atomicMax(&g_K, v);
}

// ---------------- k_final: u = clamp(-(1 - 0.9^(K+6)) * pB), thread per float4 ------
__global__ void k_final(float* __restrict__ out) {
    int idx = blockIdx.x * 256 + threadIdx.x;    // over BATCH*CD/4 float4s
    int n = g_K + 6;
    float f = -(1.0f - powf(0.9f, (float)n));
    float4 v = ((const float4*)g_pB)[idx];
    float4 u;
    u.x = fminf(fmaxf(f * v.x, -1.0f), 1.0f);
    u.y = fminf(fmaxf(f * v.y, -1.0f), 1.0f);
    u.z = fminf(fmaxf(f * v.z, -1.0f), 1.0f);
    u.w = fminf(fmaxf(f * v.w, -1.0f), 1.0f);
    ((float4*)out)[idx] = u;
}

// ---------------------------------------------------------------------------
extern "C" void kernel_launch(void* const* d_in, const int* in_sizes, int n_in,
                              void* d_out, int out_size) {
    const float* x  = (const float*)d_in[0];
    const float* t  = (const float*)d_in[1];
    const float* W1 = (const float*)d_in[2];
    const float* b1 = (const float*)d_in[3];
    const float* W2 = (const float*)d_in[4];
    const float* b2 = (const float*)d_in[5];
    const float* W3 = (const float*)d_in[6];
    const float* b3 = (const float*)d_in[7];
    const float* Bm = (const float*)d_in[8];
    float* out = (float*)d_out;

    cudaFuncSetAttribute(k_mlp, cudaFuncAttributeMaxDynamicSharedMemorySize, SM_TOTAL);

    k_prep<<<17, 256>>>(W3, b3, Bm);
    k_wcvt<<<6, 256>>>(W1, W2);
    k_mlp<<<BATCH / 128, 256, SM_TOTAL>>>(x, t, W1, b1, b2);
    k_count<<<BATCH / 256, 256>>>();
    k_final<<<BATCH * CD / 4 / 256, 256>>>(out);
}

// round 17
// speedup vs baseline: 2.7152x; 1.0014x over previous
#include <cuda_runtime.h>
#include <cuda_bf16.h>
#include <math.h>
#include <cstdint>

#define BATCH 131072
#define SD 64
#define CD 16
#define HID 256

// ---------------- smem layout (bytes) ----------------
#define SM_A2H   0         // 128 rows x 264 halves (528B stride) = 67584
#define SM_A2L   67584
#define SM_WH    135168    // 256 n-rows x 72 halves (144B stride) = 36864
#define SM_WL    172032
#define SM_W3H   135168    // reuse W buffer: 16 x 264 halves (528B) = 8448
#define SM_W3L   143616
#define SM_B1    208896    // 256 f32
#define SM_B2    209920    // 256 f32
#define SM_B3B   210944    // 16 f32
#define SM_TOTAL 211008

// ---------------- scratch globals ----------------
__device__ float g_W3B[HID * CD];
__device__ float g_b3B[CD];
__device__ float g_pB[BATCH * CD];
__device__ int   g_K;
__device__ int   g_done;
// pre-converted weight images (exact byte images of the smem staging regions)
__device__ __align__(16) unsigned char g_Wcvt[5][2][36864];  // chunks: W1, W2 k0..3
__device__ __align__(16) unsigned char g_W3cvt[2][8448];     // W3B^T tile hi/lo

// ---------------- helpers ----------------
__device__ __forceinline__ uint32_t smem_u32(const void* p) {
    uint32_t a;
    asm("{ .reg .u64 t; cvta.to.shared.u64 t, %1; cvt.u32.u64 %0, t; }" : "=r"(a) : "l"(p));
    return a;
}
#define CPA16(dst, src) asm volatile("cp.async.cg.shared.global [%0], [%1], 16;" :: "r"((uint32_t)(dst)), "l"(src))
#define CPA_COMMIT()    asm volatile("cp.async.commit_group;" ::: "memory")
#define CPA_WAIT0()     asm volatile("cp.async.wait_group 0;" ::: "memory")

// split (a,b) f32 pair into packed bf16x2 hi + lo (residual)
__device__ __forceinline__ void split2(float a, float b, uint32_t& hi, uint32_t& lo) {
    __nv_bfloat16 ha = __float2bfloat16(a), hb = __float2bfloat16(b);
    float ra = a - __bfloat162float(ha);
    float rb = b - __bfloat162float(hb);
    __nv_bfloat16 la = __float2bfloat16(ra), lb = __float2bfloat16(rb);
    hi = ((uint32_t)__bfloat16_as_ushort(hb) << 16) | (uint32_t)__bfloat16_as_ushort(ha);
    lo = ((uint32_t)__bfloat16_as_ushort(lb) << 16) | (uint32_t)__bfloat16_as_ushort(la);
}

#define LDSM4(v, addr) \
    asm volatile("ldmatrix.sync.aligned.m8n8.x4.shared.b16 {%0,%1,%2,%3}, [%4];" \
        : "=r"((v)[0]), "=r"((v)[1]), "=r"((v)[2]), "=r"((v)[3]) : "r"(addr))

#define MMA(d, a, b0, b1) \
    asm volatile("mma.sync.aligned.m16n8k16.row.col.f32.bf16.bf16.f32 " \
        "{%0,%1,%2,%3}, {%4,%5,%6,%7}, {%8,%9}, {%0,%1,%2,%3};" \
        : "+f"((d)[0]), "+f"((d)[1]), "+f"((d)[2]), "+f"((d)[3]) \
        : "r"((a)[0]), "r"((a)[1]), "r"((a)[2]), "r"((a)[3]), "r"(b0), "r"(b1))

// ---------------- k_prep: W3B = W3 @ Bmat, 16-row partition per block ----------------
__global__ void k_prep(const float* __restrict__ W3, const float* __restrict__ b3,
                       const float* __restrict__ Bm) {
    __shared__ float W3s[16 * 68];   // 16 rows x 64, stride 68 (skewed)
    __shared__ float Bs[64 * 16];
    int blk = blockIdx.x;
    int tid = threadIdx.x;
    if (blk < 16) {
        int r0 = blk * 16;
        {   // stage 16 W3 rows (4 KB) + full Bmat (4 KB), coalesced
            int row = tid >> 4, q = tid & 15;
            ((float4*)(W3s + row * 68))[q] = ((const float4*)(W3 + (r0 + row) * SD))[q];
            ((float4*)Bs)[tid] = ((const float4*)Bm)[tid];
        }
        __syncthreads();
        int r = tid >> 4, j = tid & 15;
        float a = 0.0f;
        const float* row = &W3s[r * 68];
#pragma unroll
        for (int d = 0; d < SD; d++) a = fmaf(row[d], Bs[d * CD + j], a);
        g_W3B[(r0 + r) * CD + j] = a;
    } else {
        if (tid < CD) {
            float a = 0.0f;
            for (int d = 0; d < SD; d++) a = fmaf(b3[d], Bm[d * CD + tid], a);
            g_b3B[tid] = a;
        }
        if (tid == 0) { g_K = 0; g_done = 0; }
    }
}

// ---------------- k_wcvt: convert weights to fragment-layout bf16 hi/lo once ----------
__global__ void k_wcvt(const float* __restrict__ W1, const float* __restrict__ W2) {
    int c = blockIdx.x;
    int n = threadIdx.x;
    if (c < 5) {
        const float* W = (c == 0) ? W1 : W2;
        int krow0 = (c == 0) ? 0 : (c - 1) * 64;
#pragma unroll
        for (int it = 0; it < 8; it++) {
            int kb = krow0 + it * 8;
            uint32_t h[4], l[4];
#pragma unroll
            for (int q = 0; q < 4; q++) {
                float w0 = W[(kb + 2 * q) * HID + n];
                float w1 = W[(kb + 2 * q + 1) * HID + n];
                split2(w0, w1, h[q], l[q]);
            }
            *(uint4*)(g_Wcvt[c][0] + n * 144 + it * 16) = make_uint4(h[0], h[1], h[2], h[3]);
            *(uint4*)(g_Wcvt[c][1] + n * 144 + it * 16) = make_uint4(l[0], l[1], l[2], l[3]);
        }
    } else {
#pragma unroll
        for (int it = 0; it < 8; it++) {
            int pid = n + it * 256;
            int nn = pid & 15, k2 = pid >> 4;
            float v0 = g_W3B[(2 * k2) * CD + nn];
            float v1 = g_W3B[(2 * k2 + 1) * CD + nn];
            uint32_t hi, lo;
            split2(v0, v1, hi, lo);
            *(uint32_t*)(g_W3cvt[0] + nn * 528 + k2 * 4) = hi;
            *(uint32_t*)(g_W3cvt[1] + nn * 528 + k2 * 4) = lo;
        }
    }
}

// stage pre-converted W chunk into smem via cp.async (no ALU)
__device__ __forceinline__ void stage_wchunk(uint32_t smb, int c, int tid) {
    const uint4* sH = (const uint4*)g_Wcvt[c][0];
    const uint4* sL = (const uint4*)g_Wcvt[c][1];
#pragma unroll
    for (int i = tid; i < 2304; i += 256) {
        CPA16(smb + SM_WH + i * 16, sH + i);
        CPA16(smb + SM_WL + i * 16, sL + i);
    }
    CPA_COMMIT();
}

// ---------------- fused MLP via mma.sync (R13 winner, unchanged) ----------------
__global__ void __launch_bounds__(256, 1) k_mlp(
    const float* __restrict__ x, const float* __restrict__ t,
    const float* __restrict__ W1, const float* __restrict__ b1,
    const float* __restrict__ b2)
{
    extern __shared__ char sm[];
    uint32_t smb = smem_u32(sm);
    int tid = threadIdx.x, wid = tid >> 5, lid = tid & 31;
    int slab = wid * 16;
    int row0 = blockIdx.x * 128;
    int r0 = lid >> 2, cq = 2 * (lid & 3);

    // issue W1 chunk copy immediately (overlaps everything below)
    stage_wchunk(smb, 0, tid);

    // coop: biases
    float t0 = t[0];
    ((float*)(sm + SM_B1))[tid] = fmaf(t0, W1[64 * HID + tid], b1[tid]);
    ((float*)(sm + SM_B2))[tid] = b2[tid];
    if (tid < CD) ((float*)(sm + SM_B3B))[tid] = g_b3B[tid];

    // per-warp: stage own 16 rows of X into own region of A2H, stride 68 f32
    float* Xs = (float*)(sm + SM_A2H + wid * 8448);
#pragma unroll
    for (int i = 0; i < 8; i++) {
        int fid = i * 32 + lid;
        int r = fid >> 4, c4 = fid & 15;
        float4 v = *(const float4*)&x[(row0 + slab + r) * SD + c4 * 4];
        *(float4*)&Xs[r * 68 + c4 * 4] = v;
    }
    __syncwarp();

    // X fragments (bf16 hi/lo) in regs: 4 k-tiles
    uint32_t xh[4][4], xl[4][4];
#pragma unroll
    for (int kt = 0; kt < 4; kt++) {
        int cb = kt * 16 + cq;
        float2 v00 = *(float2*)&Xs[r0 * 68 + cb];
        float2 v10 = *(float2*)&Xs[(r0 + 8) * 68 + cb];
        float2 v01 = *(float2*)&Xs[r0 * 68 + cb + 8];
        float2 v11 = *(float2*)&Xs[(r0 + 8) * 68 + cb + 8];
        split2(v00.x, v00.y, xh[kt][0], xl[kt][0]);
        split2(v10.x, v10.y, xh[kt][1], xl[kt][1]);
        split2(v01.x, v01.y, xh[kt][2], xl[kt][2]);
        split2(v11.x, v11.y, xh[kt][3], xl[kt][3]);
    }
    __syncwarp();
    CPA_WAIT0();
    __syncthreads();   // W1 staged + X frags done (X region freed)

    // ---- Layer 1: D[16x256] = X @ W1 (bf16 3-product) ----
    float d[32][4];
#pragma unroll
    for (int m = 0; m < 32; m++)
#pragma unroll
        for (int q = 0; q < 4; q++) d[m][q] = 0.0f;

#pragma unroll
    for (int kt = 0; kt < 4; kt++) {
#pragma unroll
        for (int n2 = 0; n2 < 16; n2++) {
            uint32_t bh[4], bl[4];
            uint32_t brow = n2 * 16 + ((lid >> 4) << 3) + (lid & 7);
            uint32_t baddr = smb + SM_WH + brow * 144 + (kt * 16 + (lid & 8)) * 2;
            LDSM4(bh, baddr);
            LDSM4(bl, baddr + (SM_WL - SM_WH));
            MMA(d[2 * n2],     xh[kt], bh[0], bh[1]);
            MMA(d[2 * n2],     xh[kt], bl[0], bl[1]);
            MMA(d[2 * n2],     xl[kt], bh[0], bh[1]);
            MMA(d[2 * n2 + 1], xh[kt], bh[2], bh[3]);
            MMA(d[2 * n2 + 1], xh[kt], bl[2], bl[3]);
            MMA(d[2 * n2 + 1], xl[kt], bh[2], bh[3]);
        }
    }

    // ---- relu + bias1 -> A2 (warp-private smem, bf16 hi/lo) ----
    {
        const float* bs1 = (const float*)(sm + SM_B1);
#pragma unroll
        for (int m = 0; m < 32; m++) {
            int c = m * 8 + cq;
            float2 bv = *(const float2*)&bs1[c];
            float h0 = fmaxf(d[m][0] + bv.x, 0.0f);
            float h1 = fmaxf(d[m][1] + bv.y, 0.0f);
            float h2 = fmaxf(d[m][2] + bv.x, 0.0f);
            float h3 = fmaxf(d[m][3] + bv.y, 0.0f);
            uint32_t hi01, lo01, hi23, lo23;
            split2(h0, h1, hi01, lo01);
            split2(h2, h3, hi23, lo23);
            int ra = slab + r0;
            *(uint32_t*)(sm + SM_A2H + ra * 528 + c * 2) = hi01;
            *(uint32_t*)(sm + SM_A2L + ra * 528 + c * 2) = lo01;
            *(uint32_t*)(sm + SM_A2H + (ra + 8) * 528 + c * 2) = hi23;
            *(uint32_t*)(sm + SM_A2L + (ra + 8) * 528 + c * 2) = lo23;
        }
    }
    __syncthreads();

    // zero accum for layer 2
#pragma unroll
    for (int m = 0; m < 32; m++)
#pragma unroll
        for (int q = 0; q < 4; q++) d[m][q] = 0.0f;

    // ---- Layer 2: 4 K-chunks of 64 (bf16 3-product), cp.async staging ----
#pragma unroll 1
    for (int kc = 0; kc < 4; kc++) {
        stage_wchunk(smb, 1 + kc, tid);
        CPA_WAIT0();
        __syncthreads();
#pragma unroll
        for (int kt = 0; kt < 4; kt++) {
            uint32_t ah[4], al[4];
            uint32_t arow = slab + (lid & 15);
            uint32_t acol = kc * 64 + kt * 16 + ((lid >> 4) << 3);
            uint32_t aaddr = smb + SM_A2H + arow * 528 + acol * 2;
            LDSM4(ah, aaddr);
            LDSM4(al, aaddr + (SM_A2L - SM_A2H));
#pragma unroll
            for (int n2 = 0; n2 < 16; n2++) {
                uint32_t bh[4], bl[4];
                uint32_t brow = n2 * 16 + ((lid >> 4) << 3) + (lid & 7);
                uint32_t baddr = smb + SM_WH + brow * 144 + (kt * 16 + (lid & 8)) * 2;
                LDSM4(bh, baddr);
                LDSM4(bl, baddr + (SM_WL - SM_WH));
                MMA(d[2 * n2],     ah, bh[0], bh[1]);
                MMA(d[2 * n2],     ah, bl[0], bl[1]);
                MMA(d[2 * n2],     al, bh[0], bh[1]);
                MMA(d[2 * n2 + 1], ah, bh[2], bh[3]);
                MMA(d[2 * n2 + 1], ah, bl[2], bl[3]);
                MMA(d[2 * n2 + 1], al, bh[2], bh[3]);
            }
        }
        __syncthreads();
    }

    // ---- issue W3B^T tile copy (overlaps with A3 fragment compute) ----
    {
        const uint4* sH = (const uint4*)g_W3cvt[0];
        const uint4* sL = (const uint4*)g_W3cvt[1];
#pragma unroll
        for (int i = tid; i < 528; i += 256) {
            CPA16(smb + SM_W3H + i * 16, sH + i);
            CPA16(smb + SM_W3L + i * 16, sL + i);
        }
        CPA_COMMIT();
    }

    // ---- relu + bias2 -> A3 fragments (bf16 hi/lo) ----
    uint32_t a3h[16][4], a3l[16][4];
    {
        const float* bs2 = (const float*)(sm + SM_B2);
#pragma unroll
        for (int g = 0; g < 16; g++) {
#pragma unroll
            for (int hh = 0; hh < 2; hh++) {
                int m = 2 * g + hh;
                int c = m * 8 + cq;
                float2 bv = *(const float2*)&bs2[c];
                float h0 = fmaxf(d[m][0] + bv.x, 0.0f);
                float h1 = fmaxf(d[m][1] + bv.y, 0.0f);
                float h2 = fmaxf(d[m][2] + bv.x, 0.0f);
                float h3 = fmaxf(d[m][3] + bv.y, 0.0f);
                split2(h0, h1, a3h[g][2 * hh],     a3l[g][2 * hh]);
                split2(h2, h3, a3h[g][2 * hh + 1], a3l[g][2 * hh + 1]);
            }
        }
    }
    CPA_WAIT0();
    __syncthreads();

    // ---- Layer 3: pB[16x16] = H2 @ W3B (bf16 3-product) ----
    float d3a[4] = {0.f, 0.f, 0.f, 0.f};
    float d3b[4] = {0.f, 0.f, 0.f, 0.f};
#pragma unroll
    for (int g = 0; g < 16; g++) {
        uint32_t bh[4], bl[4];
        uint32_t brow = ((lid >> 4) << 3) + (lid & 7);
        uint32_t baddr = smb + SM_W3H + brow * 528 + (g * 16 + (lid & 8)) * 2;
        LDSM4(bh, baddr);
        LDSM4(bl, baddr + (SM_W3L - SM_W3H));
        MMA(d3a, a3h[g], bh[0], bh[1]);
        MMA(d3a, a3h[g], bl[0], bl[1]);
        MMA(d3a, a3l[g], bh[0], bh[1]);
        MMA(d3b, a3h[g], bh[2], bh[3]);
        MMA(d3b, a3h[g], bl[2], bl[3]);
        MMA(d3b, a3l[g], bh[2], bh[3]);
    }

    // ---- epilogue: add b3B, store pB ----
    {
        const float* b3s = (const float*)(sm + SM_B3B);
        float2 bva = *(const float2*)&b3s[cq];
        float2 bvb = *(const float2*)&b3s[8 + cq];
        int r = row0 + slab + r0;
        float2 v;
        v = make_float2(d3a[0] + bva.x, d3a[1] + bva.y);
        *(float2*)&g_pB[r * CD + cq] = v;
        v = make_float2(d3b[0] + bvb.x, d3b[1] + bvb.y);
        *(float2*)&g_pB[r * CD + 8 + cq] = v;
        v = make_float2(d3a[2] + bva.x, d3a[3] + bva.y);
        *(float2*)&g_pB[(r + 8) * CD + cq] = v;
        v = make_float2(d3b[2] + bvb.x, d3b[3] + bvb.y);
        *(float2*)&g_pB[(r + 8) * CD + 8 + cq] = v;
    }
}

// ---------------- k_tail: analytic count + grid spin-sync + closed-form final -------
// Phase 1 (analytic, fp32): clamp-event segment walk (R16, exact on this data).
// Grid sync: 512 blocks, no smem, <=64 regs -> >=4 blocks/SM co-resident (single wave).
// Phase 2: u = clamp(-(1 - 0.9^(K+6)) * pB) from pb already in registers.
__global__ void __launch_bounds__(256) k_tail(float* __restrict__ out) {
    int row = blockIdx.x * 256 + threadIdx.x;
    const float4* pbp = (const float4*)&g_pB[row * CD];
    float4 pv[4];
    float pb2[16], nj[16];
#pragma unroll
    for (int q = 0; q < 4; q++) {
        pv[q] = pbp[q];
        float c[4] = {pv[q].x, pv[q].y, pv[q].z, pv[q].w};
#pragma unroll
        for (int e = 0; e < 4; e++) {
            int j = 4 * q + e;
            float ap = fabsf(c[e]);
            pb2[j] = c[e] * c[e];
            nj[j] = (ap > 1.0f)
                ? floorf(logf(1.0f - 1.0f / ap) * -9.49122334f) + 1.0f
                : 1e30f;
        }
    }

    float A = 0.0f;
#pragma unroll
    for (int j = 0; j < 16; j++) A += pb2[j];

    int K = 200;
    float nstart = 1.0f;
    for (int it = 0; it < 17; it++) {
        float nev = 1e30f;
#pragma unroll
        for (int j = 0; j < 16; j++)
            if (nj[j] >= nstart) nev = fminf(nev, nj[j]);
        int n0;
        if (A < 1e-30f) {
            n0 = (int)nstart;
        } else {
            float L = logf(A * 1e4f) * 4.74560547f;
            n0 = (int)floorf(L) + 2;
            if (n0 < (int)nstart) n0 = (int)nstart;
        }
        if ((float)n0 <= nev || nev > 2e29f) { K = n0; break; }
#pragma unroll
        for (int j = 0; j < 16; j++)
            if (nj[j] == nev) A -= pb2[j];
        if (A < 0.0f) A = 0.0f;
        nstart = nev + 1.0f;
    }
    if (K > 200) K = 200;
    if (K < 1) K = 1;

    int v = K;
#pragma unroll
    for (int o = 16; o > 0; o >>= 1)
        v = max(v, __shfl_xor_sync(0xffffffffu, v, o));
    if ((threadIdx.x & 31) == 0) atomicMax(&g_K, v);

    // ---- grid sync ----
    __syncthreads();
    if (threadIdx.x == 0) {
        __threadfence();
        atomicAdd(&g_done, 1);
        while (atomicAdd(&g_done, 0) < (int)gridDim.x) __nanosleep(64);
    }
    __syncthreads();

    // ---- phase 2: closed-form final from global K, pb in registers ----
    int n = *((volatile int*)&g_K) + 6;
    float f = -(1.0f - powf(0.9f, (float)n));
    float4* op = (float4*)&out[row * CD];
#pragma unroll
    for (int q = 0; q < 4; q++) {
        float4 w;
        w.x = fminf(fmaxf(f * pv[q].x, -1.0f), 1.0f);
        w.y = fminf(fmaxf(f * pv[q].y, -1.0f), 1.0f);
        w.z = fminf(fmaxf(f * pv[q].z, -1.0f), 1.0f);
        w.w = fminf(fmaxf(f * pv[q].w, -1.0f), 1.0f);
        op[q] = w;
    }
}

// ---------------------------------------------------------------------------
extern "C" void kernel_launch(void* const* d_in, const int* in_sizes, int n_in,
                              void* d_out, int out_size) {
    const float* x  = (const float*)d_in[0];
    const float* t  = (const float*)d_in[1];
    const float* W1 = (const float*)d_in[2];
    const float* b1 = (const float*)d_in[3];
    const float* W2 = (const float*)d_in[4];
    const float* b2 = (const float*)d_in[5];
    const float* W3 = (const float*)d_in[6];
    const float* b3 = (const float*)d_in[7];
    const float* Bm = (const float*)d_in[8];
    float* out = (float*)d_out;

    cudaFuncSetAttribute(k_mlp, cudaFuncAttributeMaxDynamicSharedMemorySize, SM_TOTAL);

    k_prep<<<17, 256>>>(W3, b3, Bm);
    k_wcvt<<<6, 256>>>(W1, W2);
    k_mlp<<<BATCH / 128, 256, SM_TOTAL>>>(x, t, W1, b1, b2);
    k_tail<<<BATCH / 256, 256>>>(out);
}